// round 3
// baseline (speedup 1.0000x reference)
#include <cuda_runtime.h>

#define N_NODES 100000
#define N_EDGES 3200000
#define SLOTS   128
#define FULL    0xffffffffu

// ---------------- static scratch (zero-init at load; self-cleaning) ----------
__device__ int    g_cnt  [N_NODES];           // reset by k_agg
__device__ int    g_slots[N_NODES * SLOTS];   // CSR-by-dst: src indices
__device__ float  g_dinv [N_NODES];
__device__ float  g_xd   [N_NODES];           // dinv[n] * x[n]
__device__ float  g_csum [N_NODES];           // reset by k_agg
__device__ float  g_h2g  [N_NODES * 32];      // dinv[n] * h2(s1[n])
__device__ float  g_thr  [64];                // breakpoints of h2(s1)
__device__ float2 g_AB   [32 * 65];           // [j][k] piecewise-linear coeffs
__device__ double g_accY [32];                // reset by k_final

// ---------------- k_prep: build piecewise-linear LUT for h2(s1) ---------------
// h2[j](s1) = sum_c lrelu(s1*w1c + b1c, 0.1) * W2[c,j]  is piecewise linear in
// s1 with breakpoints th_c = -b1c/w1c. Per interval k: h2[j] = s1*A[k][j]+B[k][j].
__global__ void k_prep(const float* __restrict__ W1, const float* __restrict__ b1,
                       const float* __restrict__ W2) {
    __shared__ float sw[64], sb[64], sth[64], ssort[64], srep[65];
    int t = threadIdx.x;
    if (t < 64) {
        float w = W1[t], b = b1[t];
        sw[t] = w; sb[t] = b;
        float th = (w == 0.f) ? 3.0e38f : (-b / w);
        sth[t] = th;
        g_thr[t] = th;
    }
    __syncthreads();
    if (t < 64) {                              // stable rank-sort (64^2, trivial)
        float th = sth[t];
        int r = 0;
        for (int c = 0; c < 64; c++) {
            float o = sth[c];
            if (o < th || (o == th && c < t)) r++;
        }
        ssort[r] = th;
    }
    __syncthreads();
    if (t <= 64) {                             // representative point per interval
        float rep;
        if (t == 0)       rep = ssort[0] - 1.0f;
        else if (t == 64) rep = ssort[63] + 1.0f;
        else              rep = 0.5f * ssort[t - 1] + 0.5f * ssort[t];
        rep = fminf(fmaxf(rep, -3.0e38f), 3.0e38f);
        srep[t] = rep;
    }
    __syncthreads();
    for (int p = t; p < 65 * 32; p += blockDim.x) {
        int k = p >> 5, j = p & 31;
        float rep = srep[k];
        float A = 0.f, B = 0.f;
        for (int c = 0; c < 64; c++) {
            float w = sw[c], b = sb[c];
            float m = (fmaf(rep, w, b) > 0.f) ? 1.0f : 0.1f;
            float wj = W2[c * 32 + j];
            A = fmaf(m * w, wj, A);
            B = fmaf(m * b, wj, B);
        }
        g_AB[j * 65 + k] = make_float2(A, B);   // j-major: bank-spread by k
    }
}

// ---------------- k_scatter: histogram + slot scatter (CSR build) -------------
__global__ void k_scatter(const int* __restrict__ src, const int* __restrict__ dst) {
    int e = blockIdx.x * blockDim.x + threadIdx.x;
    if (e >= N_EDGES) return;
    int d = dst[e], s = src[e];
    int pos = atomicAdd(&g_cnt[d], 1);
    if (pos < SLOTS) g_slots[d * SLOTS + pos] = s;
}

// ---------------- k_node_init: dinv + xd --------------------------------------
__global__ void k_node_init(const float* __restrict__ x) {
    int n = blockIdx.x * blockDim.x + threadIdx.x;
    if (n >= N_NODES) return;
    float di = rsqrtf((float)(g_cnt[n] + 1));  // +1 self loop
    g_dinv[n] = di;
    g_xd[n]   = di * x[n];
}

// ---------------- k_s1h2: warp-per-node s1 gather + csum atomics + h2 LUT -----
__global__ void k_s1h2() {
    int t = blockIdx.x * blockDim.x + threadIdx.x;
    int n = t >> 5, lane = t & 31;
    if (n >= N_NODES) return;
    int cnt = g_cnt[n]; if (cnt > SLOTS) cnt = SLOTS;
    float du = g_dinv[n];
    const int* __restrict__ row = g_slots + n * SLOTS;
    float acc = 0.f;
    for (int e = lane; e < cnt; e += 32) {
        int s = __ldg(row + e);
        acc += g_xd[s];
        atomicAdd(&g_csum[s], du);             // one per original edge
    }
    #pragma unroll
    for (int o = 16; o; o >>= 1) acc += __shfl_down_sync(FULL, acc, o);
    float s1 = du * (acc + g_xd[n]);           // + self-loop term (valid in lane0)
    s1 = __shfl_sync(FULL, s1, 0);

    // interval index = #{th_c < s1} via two ballots
    unsigned mlo = __ballot_sync(FULL, s1 > g_thr[lane]);
    unsigned mhi = __ballot_sync(FULL, s1 > g_thr[lane + 32]);
    int idx = __popc(mlo) + __popc(mhi);

    float2 ab = __ldg(&g_AB[lane * 65 + idx]); // 16KB LUT, L1-hot
    g_h2g[n * 32 + lane] = du * fmaf(s1, ab.x, ab.y);
}

// ---------------- k_agg: layer-2 gather + lrelu + weighted Y accumulation -----
// Y[f] = sum_n cw[n] * lrelu(du*agg[f] + b2[f]);  W3 applied once in k_final.
__global__ void k_agg(const float* __restrict__ b2) {
    __shared__ double sY[32];
    int t = threadIdx.x, lane = t & 31;
    if (t < 32) sY[t] = 0.0;
    __syncthreads();

    float b2l = b2[lane];
    double y = 0.0;
    int wid = blockIdx.x * (blockDim.x >> 5) + (t >> 5);
    int nw  = gridDim.x * (blockDim.x >> 5);

    for (int n = wid; n < N_NODES; n += nw) {
        int   cnt = g_cnt[n];                  // broadcast load (pre-store)
        float cs  = g_csum[n];
        float du  = g_dinv[n];
        if (lane == 0) { g_cnt[n] = 0; g_csum[n] = 0.f; }   // self-clean
        int c = cnt < SLOTS ? cnt : SLOTS;
        const int* __restrict__ row = g_slots + n * SLOTS;
        float acc = g_h2g[n * 32 + lane];      // self-loop term

        int e = 0;
        for (; e + 4 <= c; e += 4) {
            int s0 = __ldg(row + e),     s1 = __ldg(row + e + 1);
            int s2 = __ldg(row + e + 2), s3 = __ldg(row + e + 3);
            float v0 = __ldg(g_h2g + s0 * 32 + lane);
            float v1 = __ldg(g_h2g + s1 * 32 + lane);
            float v2 = __ldg(g_h2g + s2 * 32 + lane);
            float v3 = __ldg(g_h2g + s3 * 32 + lane);
            acc += (v0 + v1) + (v2 + v3);
        }
        for (; e < c; e++)
            acc += __ldg(g_h2g + __ldg(row + e) * 32 + lane);

        float v  = fmaf(acc, du, b2l);
        float a2 = v > 0.f ? v : 0.1f * v;     // leaky_relu(0.1)
        float cw = du * (cs + du);
        y += (double)(cw * a2);
    }

    atomicAdd(&sY[lane], y);                   // 8 warps -> 32 banks
    __syncthreads();
    if (t < 32) atomicAdd(&g_accY[t], sY[t]);  // 2048 blocks per address
}

// ---------------- k_final: out[j] = (Y @ W3)/N + b3 ----------------------------
__global__ void k_final(const float* __restrict__ W3, const float* __restrict__ b3,
                        float* __restrict__ out) {
    __shared__ double sY[32];
    int t = threadIdx.x;                       // 32 threads
    sY[t] = g_accY[t];
    g_accY[t] = 0.0;                           // self-clean
    __syncwarp();
    if (t < 10) {
        double s = 0.0;
        #pragma unroll
        for (int f = 0; f < 32; f++) s += sY[f] * (double)W3[f * 10 + t];
        out[t] = (float)(s * (1.0 / (double)N_NODES)) + b3[t];
    }
}

// ---------------- launch --------------------------------------------------------
extern "C" void kernel_launch(void* const* d_in, const int* in_sizes, int n_in,
                              void* d_out, int out_size) {
    const float* x   = (const float*)d_in[0];
    const int*   ei  = (const int*)  d_in[1];   // [2, E] row-major
    const float* W1  = (const float*)d_in[2];
    const float* b1  = (const float*)d_in[3];
    const float* W2  = (const float*)d_in[4];
    const float* b2  = (const float*)d_in[5];
    const float* W3  = (const float*)d_in[6];
    const float* b3  = (const float*)d_in[7];
    float* out = (float*)d_out;

    const int* src = ei;
    const int* dst = ei + N_EDGES;

    k_prep     <<<1, 256>>>(W1, b1, W2);
    k_scatter  <<<(N_EDGES + 255) / 256, 256>>>(src, dst);
    k_node_init<<<(N_NODES + 255) / 256, 256>>>(x);
    k_s1h2     <<<(N_NODES * 32 + 255) / 256, 256>>>();
    k_agg      <<<2048, 256>>>(b2);
    k_final    <<<1, 32>>>(W3, b3, out);
}

// round 4
// speedup vs baseline: 1.3514x; 1.3514x over previous
#include <cuda_runtime.h>

#define N_NODES 100000
#define N_EDGES 3200000
#define SLOTS   128
#define FULL    0xffffffffu

// ---------------- static scratch (zero-init at load; self-cleaning) ----------
__device__ int    g_cnt  [N_NODES];           // reset by k_agg
__device__ int    g_slots[N_NODES * SLOTS];   // CSR-by-dst: src indices
__device__ float  g_dinv [N_NODES];
__device__ float  g_xd   [N_NODES];           // dinv[n] * x[n]
__device__ float  g_csum [N_NODES];           // reset by k_agg
__device__ float  g_h2g  [N_NODES * 32];      // dinv[n] * h2(s1[n])
__device__ float  g_thr  [64];                // breakpoints of h2(s1)
__device__ float2 g_AB   [32 * 65];           // [j][k] piecewise-linear coeffs
__device__ double g_accY [32];                // reset by k_final

// ---------------- k_scatter: histogram + slot scatter (CSR build) -------------
__global__ void k_scatter(const int* __restrict__ src, const int* __restrict__ dst) {
    int e = blockIdx.x * blockDim.x + threadIdx.x;
    if (e >= N_EDGES) return;
    int d = dst[e], s = src[e];
    int pos = atomicAdd(&g_cnt[d], 1);
    if (pos < SLOTS) g_slots[d * SLOTS + pos] = s;
}

// ---------------- k_node_init: dinv + xd; last block builds the h2 LUT --------
// h2[j](s1) = sum_c lrelu(s1*w1c + b1c, 0.1) * W2[c,j]  is piecewise linear in
// s1 with breakpoints th_c = -b1c/w1c. Per interval k: h2[j] = s1*A[k][j]+B[k][j].
__global__ void k_node_init(const float* __restrict__ x,
                            const float* __restrict__ W1, const float* __restrict__ b1,
                            const float* __restrict__ W2) {
    __shared__ float sw[64], sb[64], sth[64], ssort[64], srep[65];
    int t = threadIdx.x;

    if (blockIdx.x == gridDim.x - 1) {        // ---- LUT builder block ----
        if (t < 64) {
            float w = W1[t], b = b1[t];
            sw[t] = w; sb[t] = b;
            float th = (w == 0.f) ? 3.0e38f : (-b / w);
            sth[t] = th;
            g_thr[t] = th;
        }
        __syncthreads();
        if (t < 64) {                          // stable rank-sort (64^2, trivial)
            float th = sth[t];
            int r = 0;
            for (int c = 0; c < 64; c++) {
                float o = sth[c];
                if (o < th || (o == th && c < t)) r++;
            }
            ssort[r] = th;
        }
        __syncthreads();
        if (t <= 64) {                         // representative point per interval
            float rep;
            if (t == 0)       rep = ssort[0] - 1.0f;
            else if (t == 64) rep = ssort[63] + 1.0f;
            else              rep = 0.5f * ssort[t - 1] + 0.5f * ssort[t];
            srep[t] = fminf(fmaxf(rep, -3.0e38f), 3.0e38f);
        }
        __syncthreads();
        for (int p = t; p < 65 * 32; p += blockDim.x) {
            int k = p >> 5, j = p & 31;
            float rep = srep[k];
            float A = 0.f, B = 0.f;
            for (int c = 0; c < 64; c++) {
                float w = sw[c], b = sb[c];
                float m = (fmaf(rep, w, b) > 0.f) ? 1.0f : 0.1f;
                float wj = W2[c * 32 + j];
                A = fmaf(m * w, wj, A);
                B = fmaf(m * b, wj, B);
            }
            g_AB[j * 65 + k] = make_float2(A, B);
        }
        return;
    }

    int n = blockIdx.x * blockDim.x + t;      // ---- node-init blocks ----
    if (n >= N_NODES) return;
    float di = rsqrtf((float)(g_cnt[n] + 1)); // +1 self loop
    g_dinv[n] = di;
    g_xd[n]   = di * x[n];
}

// ---------------- k_s1h2: warp-per-node s1 gather + csum atomics + h2 LUT -----
__global__ void k_s1h2() {
    int t = blockIdx.x * blockDim.x + threadIdx.x;
    int n = t >> 5, lane = t & 31;
    if (n >= N_NODES) return;
    int cnt = g_cnt[n]; if (cnt > SLOTS) cnt = SLOTS;
    float du = g_dinv[n];
    const int* __restrict__ row = g_slots + n * SLOTS;
    float acc = 0.f;
    for (int e = lane; e < cnt; e += 32) {
        int s = __ldg(row + e);
        acc += g_xd[s];
        atomicAdd(&g_csum[s], du);             // one per original edge
    }
    #pragma unroll
    for (int o = 16; o; o >>= 1) acc += __shfl_down_sync(FULL, acc, o);
    float s1 = du * (acc + g_xd[n]);           // + self-loop term (valid in lane0)
    s1 = __shfl_sync(FULL, s1, 0);

    // interval index = #{th_c < s1} via two ballots
    unsigned mlo = __ballot_sync(FULL, s1 > g_thr[lane]);
    unsigned mhi = __ballot_sync(FULL, s1 > g_thr[lane + 32]);
    int idx = __popc(mlo) + __popc(mhi);

    float2 ab = __ldg(&g_AB[lane * 65 + idx]); // 16KB LUT, L1-hot
    g_h2g[n * 32 + lane] = du * fmaf(s1, ab.x, ab.y);
}

// ---------------- k_agg: warp-per-node layer-2 gather + Y accumulation ---------
// Y[f] = sum_n cw[n] * lrelu(du*agg[f] + b2[f]);  W3 applied once in k_final.
__global__ void k_agg(const float* __restrict__ b2) {
    __shared__ double sY[8][32];
    int t = threadIdx.x, lane = t & 31, w = t >> 5;
    int n = blockIdx.x * 8 + w;

    float b2l = b2[lane];
    double y = 0.0;

    if (n < N_NODES) {
        int   cnt = g_cnt[n];                  // broadcast loads
        float cs  = g_csum[n];
        float du  = g_dinv[n];
        if (lane == 0) { g_cnt[n] = 0; g_csum[n] = 0.f; }   // self-clean
        int c = cnt < SLOTS ? cnt : SLOTS;
        const int* __restrict__ row = g_slots + n * SLOTS;
        float acc = g_h2g[n * 32 + lane];      // self-loop term

        int e = 0;
        for (; e + 4 <= c; e += 4) {
            int s0 = __ldg(row + e),     s1 = __ldg(row + e + 1);
            int s2 = __ldg(row + e + 2), s3 = __ldg(row + e + 3);
            float v0 = __ldg(g_h2g + s0 * 32 + lane);
            float v1 = __ldg(g_h2g + s1 * 32 + lane);
            float v2 = __ldg(g_h2g + s2 * 32 + lane);
            float v3 = __ldg(g_h2g + s3 * 32 + lane);
            acc += (v0 + v1) + (v2 + v3);
        }
        for (; e < c; e++)
            acc += __ldg(g_h2g + __ldg(row + e) * 32 + lane);

        float v  = fmaf(acc, du, b2l);
        float a2 = v > 0.f ? v : 0.1f * v;     // leaky_relu(0.1)
        float cw = du * (cs + du);
        y = (double)(cw * a2);
    }

    sY[w][lane] = y;
    __syncthreads();
    if (w == 0) {
        double s = (sY[0][lane] + sY[1][lane]) + (sY[2][lane] + sY[3][lane])
                 + (sY[4][lane] + sY[5][lane]) + (sY[6][lane] + sY[7][lane]);
        atomicAdd(&g_accY[lane], s);           // 12500 adds/address over ~50us
    }
}

// ---------------- k_final: out[j] = (Y @ W3)/N + b3 ----------------------------
__global__ void k_final(const float* __restrict__ W3, const float* __restrict__ b3,
                        float* __restrict__ out) {
    __shared__ double sY[32];
    int t = threadIdx.x;                       // 32 threads
    sY[t] = g_accY[t];
    g_accY[t] = 0.0;                           // self-clean
    __syncwarp();
    if (t < 10) {
        double s = 0.0;
        #pragma unroll
        for (int f = 0; f < 32; f++) s += sY[f] * (double)W3[f * 10 + t];
        out[t] = (float)(s * (1.0 / (double)N_NODES)) + b3[t];
    }
}

// ---------------- launch --------------------------------------------------------
extern "C" void kernel_launch(void* const* d_in, const int* in_sizes, int n_in,
                              void* d_out, int out_size) {
    const float* x   = (const float*)d_in[0];
    const int*   ei  = (const int*)  d_in[1];   // [2, E] row-major
    const float* W1  = (const float*)d_in[2];
    const float* b1  = (const float*)d_in[3];
    const float* W2  = (const float*)d_in[4];
    const float* b2  = (const float*)d_in[5];
    const float* W3  = (const float*)d_in[6];
    const float* b3  = (const float*)d_in[7];
    float* out = (float*)d_out;

    const int* src = ei;
    const int* dst = ei + N_EDGES;

    k_scatter  <<<(N_EDGES + 255) / 256, 256>>>(src, dst);                 // #1
    k_node_init<<<(N_NODES + 255) / 256 + 1, 256>>>(x, W1, b1, W2);        // #2
    k_s1h2     <<<(N_NODES * 32 + 255) / 256, 256>>>();                    // #3
    k_agg      <<<(N_NODES + 7) / 8, 256>>>(b2);                           // #4 <- profiled
    k_final    <<<1, 32>>>(W3, b3, out);                                   // #5
}

// round 5
// speedup vs baseline: 1.4744x; 1.0911x over previous
#include <cuda_runtime.h>

#define N_NODES 100000
#define N_EDGES 3200000
#define SLOTS   128
#define FULL    0xffffffffu

// ---------------- static scratch (zero-init at load; self-cleaning) ----------
__device__ int    g_cnt  [N_NODES];           // reset by k_agg
__device__ int    g_slots[N_NODES * SLOTS];   // CSR-by-dst: src indices
__device__ float  g_dinv [N_NODES];
__device__ float  g_xd   [N_NODES];           // dinv[n] * x[n]
__device__ float  g_csum [N_NODES];           // reset by k_agg
__device__ float  g_h2g  [N_NODES * 32];      // dinv[n] * h2(s1[n])
__device__ float  g_thr  [64];                // breakpoints of h2(s1)
__device__ float2 g_AB   [32 * 65];           // [j][k] piecewise-linear coeffs
__device__ double g_accYp[64 * 32];           // bucketed Y partials; reset by k_final

// ---------------- k_scatter: histogram + slot scatter (CSR build) -------------
__global__ void k_scatter(const int* __restrict__ src, const int* __restrict__ dst) {
    int e = blockIdx.x * blockDim.x + threadIdx.x;
    if (e >= N_EDGES) return;
    int d = dst[e], s = src[e];
    int pos = atomicAdd(&g_cnt[d], 1);
    if (pos < SLOTS) g_slots[d * SLOTS + pos] = s;
}

// ---------------- k_node_init: dinv + xd; last block builds the h2 LUT --------
__global__ void k_node_init(const float* __restrict__ x,
                            const float* __restrict__ W1, const float* __restrict__ b1,
                            const float* __restrict__ W2) {
    __shared__ float sw[64], sb[64], sth[64], ssort[64], srep[65];
    int t = threadIdx.x;

    if (blockIdx.x == gridDim.x - 1) {        // ---- LUT builder block ----
        if (t < 64) {
            float w = W1[t], b = b1[t];
            sw[t] = w; sb[t] = b;
            float th = (w == 0.f) ? 3.0e38f : (-b / w);
            sth[t] = th;
            g_thr[t] = th;
        }
        __syncthreads();
        if (t < 64) {                          // stable rank-sort
            float th = sth[t];
            int r = 0;
            for (int c = 0; c < 64; c++) {
                float o = sth[c];
                if (o < th || (o == th && c < t)) r++;
            }
            ssort[r] = th;
        }
        __syncthreads();
        if (t <= 64) {                         // representative point per interval
            float rep;
            if (t == 0)       rep = ssort[0] - 1.0f;
            else if (t == 64) rep = ssort[63] + 1.0f;
            else              rep = 0.5f * ssort[t - 1] + 0.5f * ssort[t];
            srep[t] = fminf(fmaxf(rep, -3.0e38f), 3.0e38f);
        }
        __syncthreads();
        for (int p = t; p < 65 * 32; p += blockDim.x) {
            int k = p >> 5, j = p & 31;
            float rep = srep[k];
            float A = 0.f, B = 0.f;
            for (int c = 0; c < 64; c++) {
                float w = sw[c], b = sb[c];
                float m = (fmaf(rep, w, b) > 0.f) ? 1.0f : 0.1f;
                float wj = W2[c * 32 + j];
                A = fmaf(m * w, wj, A);
                B = fmaf(m * b, wj, B);
            }
            g_AB[j * 65 + k] = make_float2(A, B);
        }
        return;
    }

    int n = blockIdx.x * blockDim.x + t;      // ---- node-init blocks ----
    if (n >= N_NODES) return;
    float di = rsqrtf((float)(g_cnt[n] + 1)); // +1 self loop
    g_dinv[n] = di;
    g_xd[n]   = di * x[n];
}

// ---------------- k_s1h2: warp-per-node s1 gather + csum atomics + h2 LUT -----
__global__ void k_s1h2() {
    int t = blockIdx.x * blockDim.x + threadIdx.x;
    int n = t >> 5, lane = t & 31;
    if (n >= N_NODES) return;
    int cnt = g_cnt[n]; if (cnt > SLOTS) cnt = SLOTS;
    float du = g_dinv[n];
    const int* __restrict__ row = g_slots + n * SLOTS;
    float acc = 0.f;
    for (int e = lane; e < cnt; e += 32) {
        int s = __ldg(row + e);
        acc += g_xd[s];
        atomicAdd(&g_csum[s], du);             // one per original edge
    }
    #pragma unroll
    for (int o = 16; o; o >>= 1) acc += __shfl_down_sync(FULL, acc, o);
    float s1 = du * (acc + g_xd[n]);           // + self-loop term (valid in lane0)
    s1 = __shfl_sync(FULL, s1, 0);

    unsigned mlo = __ballot_sync(FULL, s1 > g_thr[lane]);
    unsigned mhi = __ballot_sync(FULL, s1 > g_thr[lane + 32]);
    int idx = __popc(mlo) + __popc(mhi);

    float2 ab = __ldg(&g_AB[lane * 65 + idx]); // 16KB LUT, L1-hot
    g_h2g[n * 32 + lane] = du * fmaf(s1, ab.x, ab.y);
}

// ---------------- k_agg: warp-per-node vectorized gather + Y accumulation ------
// lane layout: e_sub = lane>>3 (edge within group of 4), q = lane&7 (float4 chunk).
// Each LDG.128 covers 4 edges/warp; indices prefetched 8-deep for MLP.
__global__ void k_agg(const float* __restrict__ b2) {
    __shared__ double sY[8][32];
    int t = threadIdx.x, lane = t & 31, w = t >> 5;
    int n = blockIdx.x * 8 + w;
    int e_sub = lane >> 3;
    int q     = lane & 7;

    if (n < N_NODES) {
        int   cnt = g_cnt[n];                  // broadcast loads
        float cs  = g_csum[n];
        float du  = g_dinv[n];
        if (lane == 0) { g_cnt[n] = 0; g_csum[n] = 0.f; }   // self-clean
        int c = cnt < SLOTS ? cnt : SLOTS;
        const int* __restrict__ row = g_slots + n * SLOTS;

        float4 acc = make_float4(0.f, 0.f, 0.f, 0.f);
        if (e_sub == 0)                        // self-loop term once
            acc = __ldg((const float4*)(g_h2g + n * 32) + q);

        for (int e = 0; e < c; e += 32) {      // 32 edges per pass
            int si[8];
            #pragma unroll
            for (int i = 0; i < 8; i++) {      // 8 index loads in flight
                int ee = e + 4 * i + e_sub;
                si[i] = (ee < c) ? __ldg(row + ee) : -1;
            }
            #pragma unroll
            for (int i = 0; i < 8; i++) {      // 8 pipelined LDG.128 gathers
                if (si[i] >= 0) {
                    float4 v = __ldg((const float4*)(g_h2g + si[i] * 32) + q);
                    acc.x += v.x; acc.y += v.y; acc.z += v.z; acc.w += v.w;
                }
            }
        }

        // reduce across the 4 e_sub groups; lanes 0..7 end with full f-chunk sums
        acc.x += __shfl_down_sync(FULL, acc.x, 16);
        acc.y += __shfl_down_sync(FULL, acc.y, 16);
        acc.z += __shfl_down_sync(FULL, acc.z, 16);
        acc.w += __shfl_down_sync(FULL, acc.w, 16);
        acc.x += __shfl_down_sync(FULL, acc.x, 8);
        acc.y += __shfl_down_sync(FULL, acc.y, 8);
        acc.z += __shfl_down_sync(FULL, acc.z, 8);
        acc.w += __shfl_down_sync(FULL, acc.w, 8);

        if (lane < 8) {
            float4 bb = __ldg((const float4*)b2 + lane);
            float cw = du * (cs + du);
            float v0 = fmaf(acc.x, du, bb.x); v0 = v0 > 0.f ? v0 : 0.1f * v0;
            float v1 = fmaf(acc.y, du, bb.y); v1 = v1 > 0.f ? v1 : 0.1f * v1;
            float v2 = fmaf(acc.z, du, bb.z); v2 = v2 > 0.f ? v2 : 0.1f * v2;
            float v3 = fmaf(acc.w, du, bb.w); v3 = v3 > 0.f ? v3 : 0.1f * v3;
            sY[w][lane * 4 + 0] = (double)(cw * v0);
            sY[w][lane * 4 + 1] = (double)(cw * v1);
            sY[w][lane * 4 + 2] = (double)(cw * v2);
            sY[w][lane * 4 + 3] = (double)(cw * v3);
        }
    } else if (lane < 8) {
        sY[w][lane * 4 + 0] = 0.0; sY[w][lane * 4 + 1] = 0.0;
        sY[w][lane * 4 + 2] = 0.0; sY[w][lane * 4 + 3] = 0.0;
    }

    __syncthreads();
    if (w == 0) {
        double s = 0.0;
        #pragma unroll
        for (int ww = 0; ww < 8; ww++) s += sY[ww][lane];
        atomicAdd(&g_accYp[(blockIdx.x & 63) * 32 + lane], s);  // <=196/address
    }
}

// ---------------- k_final: fold buckets, out[j] = (Y @ W3)/N + b3 --------------
__global__ void k_final(const float* __restrict__ W3, const float* __restrict__ b3,
                        float* __restrict__ out) {
    __shared__ double sY[32];
    int t = threadIdx.x;                       // 32 threads
    double s = 0.0;
    #pragma unroll 8
    for (int b = 0; b < 64; b++) {
        s += g_accYp[b * 32 + t];
        g_accYp[b * 32 + t] = 0.0;             // self-clean
    }
    sY[t] = s;
    __syncwarp();
    if (t < 10) {
        double r = 0.0;
        #pragma unroll
        for (int f = 0; f < 32; f++) r += sY[f] * (double)W3[f * 10 + t];
        out[t] = (float)(r * (1.0 / (double)N_NODES)) + b3[t];
    }
}

// ---------------- launch --------------------------------------------------------
extern "C" void kernel_launch(void* const* d_in, const int* in_sizes, int n_in,
                              void* d_out, int out_size) {
    const float* x   = (const float*)d_in[0];
    const int*   ei  = (const int*)  d_in[1];   // [2, E] row-major
    const float* W1  = (const float*)d_in[2];
    const float* b1  = (const float*)d_in[3];
    const float* W2  = (const float*)d_in[4];
    const float* b2  = (const float*)d_in[5];
    const float* W3  = (const float*)d_in[6];
    const float* b3  = (const float*)d_in[7];
    float* out = (float*)d_out;

    const int* src = ei;
    const int* dst = ei + N_EDGES;

    k_scatter  <<<(N_EDGES + 255) / 256, 256>>>(src, dst);                 // #1
    k_node_init<<<(N_NODES + 255) / 256 + 1, 256>>>(x, W1, b1, W2);        // #2
    k_s1h2     <<<(N_NODES * 32 + 255) / 256, 256>>>();                    // #3
    k_agg      <<<(N_NODES + 7) / 8, 256>>>(b2);                           // #4 <- profiled
    k_final    <<<1, 32>>>(W3, b3, out);                                   // #5
}